// round 5
// baseline (speedup 1.0000x reference)
#include <cuda_runtime.h>

#define Tn 48
#define Sn 2048
#define Bn 256

__device__ float g_fwd[Bn];
__device__ float g_gold[Bn];

typedef unsigned long long ull;

__device__ __forceinline__ ull pack2(float lo, float hi) {
    ull r; asm("mov.b64 %0,{%1,%2};" : "=l"(r) : "f"(lo), "f"(hi)); return r;
}
__device__ __forceinline__ void fma2(ull& a, ull b, ull c) {
    asm("fma.rn.f32x2 %0,%1,%2,%0;" : "+l"(a) : "l"(b), "l"(c));
}
__device__ __forceinline__ ull add2(ull a, ull b) {
    ull r; asm("add.rn.f32x2 %0,%1,%2;" : "=l"(r) : "l"(a), "l"(b)); return r;
}
__device__ __forceinline__ void unpack2(ull v, float& lo, float& hi) {
    asm("mov.b64 {%0,%1},%2;" : "=f"(lo), "=f"(hi) : "l"(v));
}

// ---------------------------------------------------------------------------
// Forward algorithm, linear domain, exponent-only rescaling, packed f32x2 FMA.
// One block (64 threads) per batch. Thread j owns output state j; column j of
// E = exp(transitions) lives pre-packed (k-pairs) in 24 b64 registers.
// Alpha is double-buffered in shared memory, read as VOLATILE ld.shared.v2.b64
// (volatile is required: the buffer address alternates between only 2 values,
// and non-volatile asm loads get CSE'd across iterations -> stale alpha).
// One __syncthreads per step. Invariant: alpha_i[k] = Esum*ln2 + log(S_i[k]).
// ---------------------------------------------------------------------------
__global__ __launch_bounds__(64)
void crf_forward_kernel(const float* __restrict__ emis,
                        const int*   __restrict__ mask,
                        const float* __restrict__ trans,
                        const float* __restrict__ startT,
                        const float* __restrict__ endT)
{
    __shared__ __align__(16) float sP[2][64];
    __shared__ float sRed[64];

    const int b = blockIdx.x;
    const int j = threadIdx.x;
    const bool act = (j < Tn);
    const int jj = act ? j : 0;

    // E column for this thread, packed over k in pairs: Epk[p] = (E[2p][j], E[2p+1][j])
    ull Epk[Tn / 2];
    #pragma unroll
    for (int p = 0; p < Tn / 2; ++p) {
        const float elo = __expf(trans[(2 * p)     * Tn + jj]);
        const float ehi = __expf(trans[(2 * p + 1) * Tn + jj]);
        Epk[p] = pack2(elo, ehi);
    }

    const float* em_b = emis + (size_t)b * Sn * Tn;
    const int*   mk_b = mask + (size_t)b * Sn;

    // shared base address (shared state space, 32-bit)
    unsigned sbase;
    asm("{.reg .u64 t; cvta.to.shared.u64 t, %1; cvt.u32.u64 %0, t;}"
        : "=r"(sbase) : "l"((void*)sP));

    // init: S_0 = exp(start + emissions[:,0]), stored raw
    const float S0 = __expf(startT[jj] + em_b[jj]);
    sP[0][j] = S0;
    int Esum = 0;

    // prefetch pipeline (distance 4): exp(emission) precomputed off-chain
    float f0 = __expf(em_b[1 * Tn + jj]);
    float f1 = __expf(em_b[2 * Tn + jj]);
    float f2 = __expf(em_b[3 * Tn + jj]);
    float f3 = __expf(em_b[4 * Tn + jj]);
    int   m0 = mk_b[1], m1 = mk_b[2], m2 = mk_b[3], m3 = mk_b[4];

    __syncthreads();

    int cur = 0;
    #pragma unroll 2
    for (int i = 1; i < Sn; ++i) {
        const float F  = f0;
        const int   mi = m0;
        f0 = f1; f1 = f2; f2 = f3;
        m0 = m1; m1 = m2; m2 = m3;
        const int ip = (i + 4 < Sn) ? (i + 4) : (Sn - 1);
        f3 = __expf(em_b[(size_t)ip * Tn + jj]);
        m3 = mk_b[ip];

        const unsigned cb = sbase + ((unsigned)cur << 8);

        // broadcast normalizer source + own old value
        const float q0   = sP[cur][0];
        const float qown = sP[cur][j];

        // r = 2^-ilogb(q0): exact, pure integer ops
        const int  xb = __float_as_int(q0) >> 23;
        const int  eX = xb - 127;
        const float r = __int_as_float((254 - xb) << 23);
        const float Fr = F * r;                 // hides under FMA chain

        ull a0 = 0ull, a1 = 0ull, a2 = 0ull, a3 = 0ull;
        #pragma unroll
        for (int kk = 0; kk < 12; kk += 2) {
            ull qA, qB, qC, qD;
            asm volatile("ld.shared.v2.b64 {%0,%1},[%2];"
                : "=l"(qA), "=l"(qB) : "r"(cb + (unsigned)(kk * 16)));
            asm volatile("ld.shared.v2.b64 {%0,%1},[%2];"
                : "=l"(qC), "=l"(qD) : "r"(cb + (unsigned)(kk * 16 + 16)));
            fma2(a0, qA, Epk[2 * kk + 0]);
            fma2(a1, qB, Epk[2 * kk + 1]);
            fma2(a2, qC, Epk[2 * kk + 2]);
            fma2(a3, qD, Epk[2 * kk + 3]);
        }
        const ull s = add2(add2(a0, a1), add2(a2, a3));
        float slo, shi; unpack2(s, slo, shi);
        const float Qn = (slo + shi) * Fr;

        const int nxt = cur ^ 1;
        sP[nxt][j] = mi ? Qn : qown;            // branchless mask
        Esum += mi ? eX : 0;                    // exact integer magnitude
        cur = nxt;
        __syncthreads();
    }

    // finalize: fwd = Esum*ln2 + log(sum_j S[j]*exp(end[j]))
    const float v = act ? sP[cur][j] * __expf(endT[jj]) : 0.f;
    sRed[j] = v;
    __syncthreads();
    if (j == 0) {
        float tot = 0.f;
        #pragma unroll
        for (int k = 0; k < Tn; ++k) tot += sRed[k];
        g_fwd[b] = (float)((double)Esum * 0.6931471805599453
                           + (double)logf(tot));
    }
}

// ---------------------------------------------------------------------------
// Gold path score: one block per batch, strided gather + block reduce.
// tags may arrive as int32 (JAX silently downgrades int64 without x64 mode)
// or as genuine int64 — sniff the layout (odd 32-bit words all zero => int64).
// ---------------------------------------------------------------------------
__global__ __launch_bounds__(256)
void crf_gold_kernel(const float* __restrict__ emis,
                     const int*   __restrict__ tags32,
                     const int*   __restrict__ mask,
                     const float* __restrict__ trans,
                     const float* __restrict__ startT,
                     const float* __restrict__ endT)
{
    __shared__ double sred[256];
    __shared__ int    scnt[256];
    __shared__ int    s_is64;
    const int b = blockIdx.x, t = threadIdx.x;

    if (t < 32) {
        unsigned hw = (unsigned)tags32[2 * t + 1];
        #pragma unroll
        for (int off = 16; off > 0; off >>= 1)
            hw |= __shfl_down_sync(0xffffffffu, hw, off);
        if (t == 0) s_is64 = (hw == 0u) ? 1 : 0;
    }
    __syncthreads();
    const int is64 = s_is64;
    const size_t base = (size_t)b * Sn;

    const int*   mk = mask + base;
    const float* em = emis + (size_t)b * Sn * Tn;

    double acc = 0.0;
    int cnt = 0;
    for (int i = t; i < Sn; i += 256) {
        const int m = mk[i];
        cnt += m;
        if (i >= 1 && m) {
            const size_t ic = base + (size_t)i;
            const int tp = is64 ? tags32[(ic - 1) << 1] : tags32[ic - 1];
            const int tc = is64 ? tags32[ic << 1]       : tags32[ic];
            acc += (double)trans[tp * Tn + tc] + (double)em[(size_t)i * Tn + tc];
        }
    }
    sred[t] = acc;
    scnt[t] = cnt;
    __syncthreads();
    for (int s2 = 128; s2 > 0; s2 >>= 1) {
        if (t < s2) { sred[t] += sred[t + s2]; scnt[t] += scnt[t + s2]; }
        __syncthreads();
    }
    if (t == 0) {
        const int t0 = is64 ? tags32[base << 1] : tags32[base];
        double g = sred[0] + (double)startT[t0] + (double)em[t0];
        const size_t il = base + (size_t)(scnt[0] - 1);
        const int tl = is64 ? tags32[il << 1] : tags32[il];
        g += (double)endT[tl];
        g_gold[b] = (float)g;
    }
}

// ---------------------------------------------------------------------------
// Final: out = mean(fwd - gold)
// ---------------------------------------------------------------------------
__global__ __launch_bounds__(256)
void crf_final_kernel(float* __restrict__ out)
{
    __shared__ double sred[256];
    const int t = threadIdx.x;
    sred[t] = (double)g_fwd[t] - (double)g_gold[t];
    __syncthreads();
    for (int s2 = 128; s2 > 0; s2 >>= 1) {
        if (t < s2) sred[t] += sred[t + s2];
        __syncthreads();
    }
    if (t == 0) out[0] = (float)(sred[0] / (double)Bn);
}

extern "C" void kernel_launch(void* const* d_in, const int* in_sizes, int n_in,
                              void* d_out, int out_size)
{
    const float* emis   = (const float*)d_in[0];
    const int*   tags32 = (const int*)d_in[1];   // int32 OR int64 viewed as words
    const int*   mask   = (const int*)d_in[2];
    const float* trans  = (const float*)d_in[3];
    const float* startT = (const float*)d_in[4];
    const float* endT   = (const float*)d_in[5];
    float* out = (float*)d_out;

    crf_forward_kernel<<<Bn, 64>>>(emis, mask, trans, startT, endT);
    crf_gold_kernel<<<Bn, 256>>>(emis, tags32, mask, trans, startT, endT);
    crf_final_kernel<<<1, 256>>>(out);
}

// round 6
// speedup vs baseline: 1.0176x; 1.0176x over previous
#include <cuda_runtime.h>

#define Tn 48
#define Sn 2048
#define Bn 256
#define HB 128   // blocks = batch pairs

__device__ float g_fwd[Bn];
__device__ float g_gold[Bn];

typedef unsigned long long ull;

__device__ __forceinline__ ull pack2(float lo, float hi) {
    ull r; asm("mov.b64 %0,{%1,%2};" : "=l"(r) : "f"(lo), "f"(hi)); return r;
}
__device__ __forceinline__ void fma2(ull& a, ull b, ull c) {
    asm("fma.rn.f32x2 %0,%1,%2,%0;" : "+l"(a) : "l"(b), "l"(c));
}
__device__ __forceinline__ ull add2(ull a, ull b) {
    ull r; asm("add.rn.f32x2 %0,%1,%2;" : "=l"(r) : "l"(a), "l"(b)); return r;
}
__device__ __forceinline__ ull mul2(ull a, ull b) {
    ull r; asm("mul.rn.f32x2 %0,%1,%2;" : "=l"(r) : "l"(a), "l"(b)); return r;
}
__device__ __forceinline__ void unpack2(ull v, float& lo, float& hi) {
    asm("mov.b64 {%0,%1},%2;" : "=f"(lo), "=f"(hi) : "l"(v));
}

// ---------------------------------------------------------------------------
// Forward algorithm, linear domain, exponent-only rescaling, TWO BATCHES per
// block packed into f32x2 lanes. Block p handles batches (p, p+128); thread j
// owns state j for both. Shared holds pairs (S_A[k], S_B[k]); loads are C++
// ulonglong2 (LDS.128; correct ordering vs __syncthreads — no asm loads, the
// R4 CSE bug and the R5 volatile serialization are both avoided). E column is
// pre-duplicated per k: Edup[k] = (E[k][j], E[k][j]) so FFMA2 advances both
// chains per instruction. Grid=128 < #SMs: one block per SM, no contention.
// Invariant per batch: alpha_i[k] = Esum*ln2 + log(S_i[k]); FFMA2 is exact
// fp32, normalization uses only the exponent field (exact integer ops).
// ---------------------------------------------------------------------------
__global__ __launch_bounds__(64, 1)
void crf_forward_kernel(const float* __restrict__ emis,
                        const int*   __restrict__ mask,
                        const float* __restrict__ trans,
                        const float* __restrict__ startT,
                        const float* __restrict__ endT)
{
    __shared__ __align__(16) ull sPu[2][64];
    __shared__ float sRedA[64];
    __shared__ float sRedB[64];

    const int p = blockIdx.x;
    const int bA = p, bB = p + HB;
    const int j = threadIdx.x;
    const bool act = (j < Tn);
    const int jj = act ? j : 0;

    // E column duplicated per k: Edup[k] = (E[k][j], E[k][j])
    ull Edup[Tn];
    #pragma unroll
    for (int k = 0; k < Tn; ++k) {
        const float e = __expf(trans[k * Tn + jj]);
        Edup[k] = pack2(e, e);
    }

    const float* emA = emis + (size_t)bA * Sn * Tn;
    const float* emB = emis + (size_t)bB * Sn * Tn;
    const int*   mkA = mask + (size_t)bA * Sn;
    const int*   mkB = mask + (size_t)bB * Sn;

    // init: S_0 = exp(start + emissions[:,0]) per batch, packed
    {
        const float sa = __expf(startT[jj] + emA[jj]);
        const float sb = __expf(startT[jj] + emB[jj]);
        sPu[0][j] = pack2(sa, sb);
    }
    int EsA = 0, EsB = 0;

    // prefetch pipeline (distance 4): exp(emission) + mask for both batches
    float fA0 = __expf(emA[1 * Tn + jj]), fB0 = __expf(emB[1 * Tn + jj]);
    float fA1 = __expf(emA[2 * Tn + jj]), fB1 = __expf(emB[2 * Tn + jj]);
    float fA2 = __expf(emA[3 * Tn + jj]), fB2 = __expf(emB[3 * Tn + jj]);
    float fA3 = __expf(emA[4 * Tn + jj]), fB3 = __expf(emB[4 * Tn + jj]);
    int mA0 = mkA[1], mA1 = mkA[2], mA2 = mkA[3], mA3 = mkA[4];
    int mB0 = mkB[1], mB1 = mkB[2], mB2 = mkB[3], mB3 = mkB[4];

    __syncthreads();

    int cur = 0;
    #pragma unroll 4
    for (int i = 1; i < Sn; ++i) {
        const float FA = fA0, FB = fB0;
        const int   miA = mA0, miB = mB0;
        fA0 = fA1; fA1 = fA2; fA2 = fA3;
        fB0 = fB1; fB1 = fB2; fB2 = fB3;
        mA0 = mA1; mA1 = mA2; mA2 = mA3;
        mB0 = mB1; mB1 = mB2; mB2 = mB3;
        const int ip = (i + 4 < Sn) ? (i + 4) : (Sn - 1);
        fA3 = __expf(emA[(size_t)ip * Tn + jj]);
        fB3 = __expf(emB[(size_t)ip * Tn + jj]);
        mA3 = mkA[ip];
        mB3 = mkB[ip];

        const ulonglong2* __restrict__ p2 = (const ulonglong2*)sPu[cur];

        // matvec for both batches: 24 LDS.128, 48 FFMA2, 8 accumulators
        ull a0 = 0ull, a1 = 0ull, a2 = 0ull, a3 = 0ull;
        ull a4 = 0ull, a5 = 0ull, a6 = 0ull, a7 = 0ull;
        ull q00 = 0ull;     // pair for k=0 (normalizer source)
        #pragma unroll
        for (int m = 0; m < 24; m += 4) {
            const ulonglong2 qa = p2[m + 0];
            const ulonglong2 qb = p2[m + 1];
            const ulonglong2 qc = p2[m + 2];
            const ulonglong2 qd = p2[m + 3];
            if (m == 0) q00 = qa.x;
            fma2(a0, qa.x, Edup[2 * m + 0]);
            fma2(a1, qa.y, Edup[2 * m + 1]);
            fma2(a2, qb.x, Edup[2 * m + 2]);
            fma2(a3, qb.y, Edup[2 * m + 3]);
            fma2(a4, qc.x, Edup[2 * m + 4]);
            fma2(a5, qc.y, Edup[2 * m + 5]);
            fma2(a6, qd.x, Edup[2 * m + 6]);
            fma2(a7, qd.y, Edup[2 * m + 7]);
        }
        const ull s = add2(add2(add2(a0, a1), add2(a2, a3)),
                           add2(add2(a4, a5), add2(a6, a7)));

        // per-batch normalizer from exponent of S[0] (exact integer ops)
        float SA0, SB0; unpack2(q00, SA0, SB0);
        const int xbA = __float_as_int(SA0) >> 23;
        const int xbB = __float_as_int(SB0) >> 23;
        const float rA = __int_as_float((254 - xbA) << 23);
        const float rB = __int_as_float((254 - xbB) << 23);
        const ull Fr = pack2(FA * rA, FB * rB);

        const ull Qn2 = mul2(s, Fr);
        float qnA, qnB; unpack2(Qn2, qnA, qnB);

        // branchless mask per half
        const ull qown = sPu[cur][j];
        float qoA, qoB; unpack2(qown, qoA, qoB);
        const float outA = miA ? qnA : qoA;
        const float outB = miB ? qnB : qoB;

        const int nxt = cur ^ 1;
        sPu[nxt][j] = pack2(outA, outB);
        EsA += miA ? (xbA - 127) : 0;
        EsB += miB ? (xbB - 127) : 0;
        cur = nxt;
        __syncthreads();
    }

    // finalize: fwd = Esum*ln2 + log(sum_j S[j]*exp(end[j])) per batch
    {
        float SA, SB; unpack2(sPu[cur][j], SA, SB);
        const float w = act ? __expf(endT[jj]) : 0.f;
        sRedA[j] = SA * w;
        sRedB[j] = SB * w;
    }
    __syncthreads();
    if (j == 0) {
        float totA = 0.f, totB = 0.f;
        #pragma unroll
        for (int k = 0; k < Tn; ++k) { totA += sRedA[k]; totB += sRedB[k]; }
        g_fwd[bA] = (float)((double)EsA * 0.6931471805599453 + (double)logf(totA));
        g_fwd[bB] = (float)((double)EsB * 0.6931471805599453 + (double)logf(totB));
    }
}

// ---------------------------------------------------------------------------
// Gold path score: one block per batch, strided gather + block reduce.
// tags may arrive as int32 (JAX silently downgrades int64 without x64 mode)
// or as genuine int64 — sniff the layout (odd 32-bit words all zero => int64).
// ---------------------------------------------------------------------------
__global__ __launch_bounds__(256)
void crf_gold_kernel(const float* __restrict__ emis,
                     const int*   __restrict__ tags32,
                     const int*   __restrict__ mask,
                     const float* __restrict__ trans,
                     const float* __restrict__ startT,
                     const float* __restrict__ endT)
{
    __shared__ double sred[256];
    __shared__ int    scnt[256];
    __shared__ int    s_is64;
    const int b = blockIdx.x, t = threadIdx.x;

    if (t < 32) {
        unsigned hw = (unsigned)tags32[2 * t + 1];
        #pragma unroll
        for (int off = 16; off > 0; off >>= 1)
            hw |= __shfl_down_sync(0xffffffffu, hw, off);
        if (t == 0) s_is64 = (hw == 0u) ? 1 : 0;
    }
    __syncthreads();
    const int is64 = s_is64;
    const size_t base = (size_t)b * Sn;

    const int*   mk = mask + base;
    const float* em = emis + (size_t)b * Sn * Tn;

    double acc = 0.0;
    int cnt = 0;
    for (int i = t; i < Sn; i += 256) {
        const int m = mk[i];
        cnt += m;
        if (i >= 1 && m) {
            const size_t ic = base + (size_t)i;
            const int tp = is64 ? tags32[(ic - 1) << 1] : tags32[ic - 1];
            const int tc = is64 ? tags32[ic << 1]       : tags32[ic];
            acc += (double)trans[tp * Tn + tc] + (double)em[(size_t)i * Tn + tc];
        }
    }
    sred[t] = acc;
    scnt[t] = cnt;
    __syncthreads();
    for (int s2 = 128; s2 > 0; s2 >>= 1) {
        if (t < s2) { sred[t] += sred[t + s2]; scnt[t] += scnt[t + s2]; }
        __syncthreads();
    }
    if (t == 0) {
        const int t0 = is64 ? tags32[base << 1] : tags32[base];
        double g = sred[0] + (double)startT[t0] + (double)em[t0];
        const size_t il = base + (size_t)(scnt[0] - 1);
        const int tl = is64 ? tags32[il << 1] : tags32[il];
        g += (double)endT[tl];
        g_gold[b] = (float)g;
    }
}

// ---------------------------------------------------------------------------
// Final: out = mean(fwd - gold)
// ---------------------------------------------------------------------------
__global__ __launch_bounds__(256)
void crf_final_kernel(float* __restrict__ out)
{
    __shared__ double sred[256];
    const int t = threadIdx.x;
    sred[t] = (double)g_fwd[t] - (double)g_gold[t];
    __syncthreads();
    for (int s2 = 128; s2 > 0; s2 >>= 1) {
        if (t < s2) sred[t] += sred[t + s2];
        __syncthreads();
    }
    if (t == 0) out[0] = (float)(sred[0] / (double)Bn);
}

extern "C" void kernel_launch(void* const* d_in, const int* in_sizes, int n_in,
                              void* d_out, int out_size)
{
    const float* emis   = (const float*)d_in[0];
    const int*   tags32 = (const int*)d_in[1];   // int32 OR int64 viewed as words
    const int*   mask   = (const int*)d_in[2];
    const float* trans  = (const float*)d_in[3];
    const float* startT = (const float*)d_in[4];
    const float* endT   = (const float*)d_in[5];
    float* out = (float*)d_out;

    crf_forward_kernel<<<HB, 64>>>(emis, mask, trans, startT, endT);
    crf_gold_kernel<<<Bn, 256>>>(emis, tags32, mask, trans, startT, endT);
    crf_final_kernel<<<1, 256>>>(out);
}

// round 7
// speedup vs baseline: 1.1722x; 1.1519x over previous
#include <cuda_runtime.h>

#define Tn 48
#define Sn 2048
#define Bn 256

__device__ float g_fwd[Bn];
__device__ float g_gold[Bn];

typedef unsigned long long ull;

__device__ __forceinline__ ull pack2(float lo, float hi) {
    ull r; asm("mov.b64 %0,{%1,%2};" : "=l"(r) : "f"(lo), "f"(hi)); return r;
}
__device__ __forceinline__ void fma2(ull& a, ull b, ull c) {
    asm("fma.rn.f32x2 %0,%1,%2,%0;" : "+l"(a) : "l"(b), "l"(c));
}
__device__ __forceinline__ ull add2(ull a, ull b) {
    ull r; asm("add.rn.f32x2 %0,%1,%2;" : "=l"(r) : "l"(a), "l"(b)); return r;
}
__device__ __forceinline__ ull mul2(ull a, ull b) {
    ull r; asm("mul.rn.f32x2 %0,%1,%2;" : "=l"(r) : "l"(a), "l"(b)); return r;
}
__device__ __forceinline__ void unpack2(ull v, float& lo, float& hi) {
    asm("mov.b64 {%0,%1},%2;" : "=f"(lo), "=f"(hi) : "l"(v));
}

// ---------------------------------------------------------------------------
// Forward algorithm: ONE WARP per batch. Lane l (<24) owns output states
// (2l, 2l+1) packed in one f32x2 accumulator. Alpha is kept in shared as
// duplicated pairs sD[k] = (a_k, a_k) so a broadcast ulonglong2 load feeds
// FFMA2 directly: acc += (a_k,a_k)*(E[k][2l],E[k][2l+1]). 48 FFMA2 per lane
// covers all 48x48 products with single-warp issue. __syncwarp (not bar.sync)
// is the only synchronization per step. Loads are plain C++ (ordered by
// __syncwarp; no asm-load CSE issue, no volatile serialization).
// Exponent-only rescaling: alpha_i[k] = Esum*ln2 + log(S_i[k]), exact.
// ---------------------------------------------------------------------------
__global__ __launch_bounds__(32)
void crf_forward_kernel(const float* __restrict__ emis,
                        const int*   __restrict__ mask,
                        const float* __restrict__ trans,
                        const float* __restrict__ startT,
                        const float* __restrict__ endT)
{
    __shared__ __align__(16) ull sD[2][Tn];

    const int b = blockIdx.x;
    const int l = threadIdx.x;
    const bool act = (l < Tn / 2);          // lanes 0..23 active
    const int j0 = act ? 2 * l     : 0;
    const int j1 = act ? 2 * l + 1 : 0;

    // Epair[k] = (E[k][j0], E[k][j1])
    ull Epair[Tn];
    #pragma unroll
    for (int k = 0; k < Tn; ++k)
        Epair[k] = pack2(__expf(trans[k * Tn + j0]),
                         __expf(trans[k * Tn + j1]));

    const float* em_b = emis + (size_t)b * Sn * Tn;
    const int*   mk_b = mask + (size_t)b * Sn;

    // init: S_0 = exp(start + em[0]); store duplicated pairs
    if (act) {
        const float s0 = __expf(startT[j0] + em_b[j0]);
        const float s1 = __expf(startT[j1] + em_b[j1]);
        ((ulonglong2*)sD[0])[l] = make_ulonglong2(pack2(s0, s0), pack2(s1, s1));
    }
    int Esum = 0;

    // prefetch (distance 4): float2 emission for (j0,j1), exp'd off-chain
    const float2* emv = (const float2*)em_b;   // index: i*24 + l
    #define EMLD(i) (emv[(size_t)(i) * (Tn / 2) + (act ? l : 0)])
    float2 t;
    t = EMLD(1); float fa0 = __expf(t.x), fb0 = __expf(t.y);
    t = EMLD(2); float fa1 = __expf(t.x), fb1 = __expf(t.y);
    t = EMLD(3); float fa2 = __expf(t.x), fb2 = __expf(t.y);
    t = EMLD(4); float fa3 = __expf(t.x), fb3 = __expf(t.y);
    int m0 = mk_b[1], m1 = mk_b[2], m2 = mk_b[3], m3 = mk_b[4];

    __syncwarp();

    int cur = 0;
    #pragma unroll 2
    for (int i = 1; i < Sn; ++i) {
        const float F0 = fa0, F1 = fb0;
        const int   mi = m0;
        fa0 = fa1; fb0 = fb1; fa1 = fa2; fb1 = fb2; fa2 = fa3; fb2 = fb3;
        m0 = m1; m1 = m2; m2 = m3;
        const int ip = (i + 4 < Sn) ? (i + 4) : (Sn - 1);
        t = EMLD(ip); fa3 = __expf(t.x); fb3 = __expf(t.y);
        m3 = mk_b[ip];

        const ulonglong2* __restrict__ p2 = (const ulonglong2*)sD[cur];

        // own old pair (for mask select): lo halves of sD[j0], sD[j1]
        const ulonglong2 own = p2[act ? l : 0];

        // matvec: 24 broadcast LDS.128, 48 FFMA2, 8 accumulators
        ull a0 = 0ull, a1 = 0ull, a2 = 0ull, a3 = 0ull;
        ull a4 = 0ull, a5 = 0ull, a6 = 0ull, a7 = 0ull;
        ull q00 = 0ull;
        #pragma unroll
        for (int m = 0; m < Tn / 2; m += 4) {
            const ulonglong2 qa = p2[m + 0];
            const ulonglong2 qb = p2[m + 1];
            const ulonglong2 qc = p2[m + 2];
            const ulonglong2 qd = p2[m + 3];
            if (m == 0) q00 = qa.x;
            fma2(a0, qa.x, Epair[2 * m + 0]);
            fma2(a1, qa.y, Epair[2 * m + 1]);
            fma2(a2, qb.x, Epair[2 * m + 2]);
            fma2(a3, qb.y, Epair[2 * m + 3]);
            fma2(a4, qc.x, Epair[2 * m + 4]);
            fma2(a5, qc.y, Epair[2 * m + 5]);
            fma2(a6, qd.x, Epair[2 * m + 6]);
            fma2(a7, qd.y, Epair[2 * m + 7]);
        }
        const ull s = add2(add2(add2(a0, a1), add2(a2, a3)),
                           add2(add2(a4, a5), add2(a6, a7)));

        // normalizer from exponent of alpha[0] (exact integer ops)
        float q0f, dum; unpack2(q00, q0f, dum);
        const int xb = __float_as_int(q0f) >> 23;
        const float r = __int_as_float((254 - xb) << 23);
        const ull Fr = pack2(F0 * r, F1 * r);

        const ull Qn2 = mul2(s, Fr);
        float qn0, qn1; unpack2(Qn2, qn0, qn1);
        float qo0, qod0; unpack2(own.x, qo0, qod0);
        float qo1, qod1; unpack2(own.y, qo1, qod1);
        const float o0 = mi ? qn0 : qo0;
        const float o1 = mi ? qn1 : qo1;

        const int nxt = cur ^ 1;
        if (act)
            ((ulonglong2*)sD[nxt])[l] =
                make_ulonglong2(pack2(o0, o0), pack2(o1, o1));
        Esum += mi ? (xb - 127) : 0;
        cur = nxt;
        __syncwarp();
    }

    // finalize: fwd = Esum*ln2 + log(sum_j S[j]*exp(end[j]))
    float v = 0.f;
    if (act) {
        const ulonglong2 fin = ((const ulonglong2*)sD[cur])[l];
        float s0, d0, s1, d1;
        unpack2(fin.x, s0, d0);
        unpack2(fin.y, s1, d1);
        v = s0 * __expf(endT[j0]) + s1 * __expf(endT[j1]);
    }
    #pragma unroll
    for (int off = 16; off > 0; off >>= 1)
        v += __shfl_xor_sync(0xffffffffu, v, off);
    if (l == 0)
        g_fwd[b] = (float)((double)Esum * 0.6931471805599453
                           + (double)logf(v));
}

// ---------------------------------------------------------------------------
// Gold path score: one block per batch, strided gather + block reduce.
// tags may arrive as int32 (JAX silently downgrades int64 without x64 mode)
// or as genuine int64 — sniff the layout (odd 32-bit words all zero => int64).
// ---------------------------------------------------------------------------
__global__ __launch_bounds__(256)
void crf_gold_kernel(const float* __restrict__ emis,
                     const int*   __restrict__ tags32,
                     const int*   __restrict__ mask,
                     const float* __restrict__ trans,
                     const float* __restrict__ startT,
                     const float* __restrict__ endT)
{
    __shared__ double sred[256];
    __shared__ int    scnt[256];
    __shared__ int    s_is64;
    const int b = blockIdx.x, t = threadIdx.x;

    if (t < 32) {
        unsigned hw = (unsigned)tags32[2 * t + 1];
        #pragma unroll
        for (int off = 16; off > 0; off >>= 1)
            hw |= __shfl_down_sync(0xffffffffu, hw, off);
        if (t == 0) s_is64 = (hw == 0u) ? 1 : 0;
    }
    __syncthreads();
    const int is64 = s_is64;
    const size_t base = (size_t)b * Sn;

    const int*   mk = mask + base;
    const float* em = emis + (size_t)b * Sn * Tn;

    double acc = 0.0;
    int cnt = 0;
    for (int i = t; i < Sn; i += 256) {
        const int m = mk[i];
        cnt += m;
        if (i >= 1 && m) {
            const size_t ic = base + (size_t)i;
            const int tp = is64 ? tags32[(ic - 1) << 1] : tags32[ic - 1];
            const int tc = is64 ? tags32[ic << 1]       : tags32[ic];
            acc += (double)trans[tp * Tn + tc] + (double)em[(size_t)i * Tn + tc];
        }
    }
    sred[t] = acc;
    scnt[t] = cnt;
    __syncthreads();
    for (int s2 = 128; s2 > 0; s2 >>= 1) {
        if (t < s2) { sred[t] += sred[t + s2]; scnt[t] += scnt[t + s2]; }
        __syncthreads();
    }
    if (t == 0) {
        const int t0 = is64 ? tags32[base << 1] : tags32[base];
        double g = sred[0] + (double)startT[t0] + (double)em[t0];
        const size_t il = base + (size_t)(scnt[0] - 1);
        const int tl = is64 ? tags32[il << 1] : tags32[il];
        g += (double)endT[tl];
        g_gold[b] = (float)g;
    }
}

// ---------------------------------------------------------------------------
// Final: out = mean(fwd - gold)
// ---------------------------------------------------------------------------
__global__ __launch_bounds__(256)
void crf_final_kernel(float* __restrict__ out)
{
    __shared__ double sred[256];
    const int t = threadIdx.x;
    sred[t] = (double)g_fwd[t] - (double)g_gold[t];
    __syncthreads();
    for (int s2 = 128; s2 > 0; s2 >>= 1) {
        if (t < s2) sred[t] += sred[t + s2];
        __syncthreads();
    }
    if (t == 0) out[0] = (float)(sred[0] / (double)Bn);
}

extern "C" void kernel_launch(void* const* d_in, const int* in_sizes, int n_in,
                              void* d_out, int out_size)
{
    const float* emis   = (const float*)d_in[0];
    const int*   tags32 = (const int*)d_in[1];   // int32 OR int64 viewed as words
    const int*   mask   = (const int*)d_in[2];
    const float* trans  = (const float*)d_in[3];
    const float* startT = (const float*)d_in[4];
    const float* endT   = (const float*)d_in[5];
    float* out = (float*)d_out;

    crf_forward_kernel<<<Bn, 32>>>(emis, mask, trans, startT, endT);
    crf_gold_kernel<<<Bn, 256>>>(emis, tags32, mask, trans, startT, endT);
    crf_final_kernel<<<1, 256>>>(out);
}

// round 8
// speedup vs baseline: 1.3937x; 1.1889x over previous
#include <cuda_runtime.h>

#define Tn 48
#define Sn 2048
#define Bn 256

__device__ float g_fwd[Bn];
__device__ float g_gold[Bn];

typedef unsigned long long ull;

__device__ __forceinline__ ull pack2(float lo, float hi) {
    ull r; asm("mov.b64 %0,{%1,%2};" : "=l"(r) : "f"(lo), "f"(hi)); return r;
}
__device__ __forceinline__ void fma2(ull& a, ull b, ull c) {
    asm("fma.rn.f32x2 %0,%1,%2,%0;" : "+l"(a) : "l"(b), "l"(c));
}
__device__ __forceinline__ ull add2(ull a, ull b) {
    ull r; asm("add.rn.f32x2 %0,%1,%2;" : "=l"(r) : "l"(a), "l"(b)); return r;
}
__device__ __forceinline__ void unpack2(ull v, float& lo, float& hi) {
    asm("mov.b64 {%0,%1},%2;" : "=f"(lo), "=f"(hi) : "l"(v));
}

// ---------------------------------------------------------------------------
// Forward algorithm, linear domain, exponent-only rescaling. R3 structure
// (64 threads / 2 warps per batch, one __syncthreads per step, alpha stored
// as plain float[64] double-buffered in shared) but the 48-FMA inner product
// is done as 24 FFMA2: alpha is read via C++ ulonglong2 loads — two adjacent
// floats ARE an f32x2 pair, so no repacking and no asm loads (avoids both the
// R4 CSE bug and the R5 volatile serialization). E column is pre-packed over
// k-pairs: Epk[p] = (E[2p][j], E[2p+1][j]).
// Invariant: alpha_i[k] = Esum*ln2 + log(S_i[k]); normalization uses only the
// exponent field of S[0] (exact integer ops, off the critical chain).
// ---------------------------------------------------------------------------
__global__ __launch_bounds__(64)
void crf_forward_kernel(const float* __restrict__ emis,
                        const int*   __restrict__ mask,
                        const float* __restrict__ trans,
                        const float* __restrict__ startT,
                        const float* __restrict__ endT)
{
    __shared__ __align__(16) float sP[2][64];
    __shared__ float sRed[64];

    const int b = blockIdx.x;
    const int j = threadIdx.x;
    const bool act = (j < Tn);
    const int jj = act ? j : 0;

    // E column for this thread, packed over k in pairs
    ull Epk[Tn / 2];
    #pragma unroll
    for (int p = 0; p < Tn / 2; ++p)
        Epk[p] = pack2(__expf(trans[(2 * p)     * Tn + jj]),
                       __expf(trans[(2 * p + 1) * Tn + jj]));

    const float* em_b = emis + (size_t)b * Sn * Tn;
    const int*   mk_b = mask + (size_t)b * Sn;

    // init: S_0 = exp(start + emissions[:,0]), stored raw
    const float S0 = __expf(startT[jj] + em_b[jj]);
    sP[0][j] = S0;
    int Esum = 0;

    // prefetch pipeline (distance 4): exp(emission) precomputed off-chain
    float f0 = __expf(em_b[1 * Tn + jj]);
    float f1 = __expf(em_b[2 * Tn + jj]);
    float f2 = __expf(em_b[3 * Tn + jj]);
    float f3 = __expf(em_b[4 * Tn + jj]);
    int   m0 = mk_b[1], m1 = mk_b[2], m2 = mk_b[3], m3 = mk_b[4];

    __syncthreads();

    int cur = 0;
    #pragma unroll 2
    for (int i = 1; i < Sn; ++i) {
        const float F  = f0;
        const int   mi = m0;
        f0 = f1; f1 = f2; f2 = f3;
        m0 = m1; m1 = m2; m2 = m3;
        const int ip = (i + 4 < Sn) ? (i + 4) : (Sn - 1);
        f3 = __expf(em_b[(size_t)ip * Tn + jj]);
        m3 = mk_b[ip];

        // alpha as f32x2 pairs: C++ LDS.128, each yields 2 packed pairs
        const ulonglong2* __restrict__ p2 = (const ulonglong2*)sP[cur];

        const float q0   = sP[cur][0];    // normalizer source (broadcast)
        const float qown = sP[cur][j];    // own old value (mask select)

        // r = 2^-ilogb(q0): exact, pure integer ops, off the FMA chain
        const int  xb = __float_as_int(q0) >> 23;
        const float r = __int_as_float((254 - xb) << 23);
        const float Fr = F * r;

        ull a0 = 0ull, a1 = 0ull, a2 = 0ull, a3 = 0ull;
        #pragma unroll
        for (int m = 0; m < 12; m += 2) {
            const ulonglong2 qa = p2[m + 0];   // pairs (4m..4m+3)
            const ulonglong2 qb = p2[m + 1];   // pairs (4m+4..4m+7)
            fma2(a0, qa.x, Epk[2 * m + 0]);
            fma2(a1, qa.y, Epk[2 * m + 1]);
            fma2(a2, qb.x, Epk[2 * m + 2]);
            fma2(a3, qb.y, Epk[2 * m + 3]);
        }
        const ull s = add2(add2(a0, a1), add2(a2, a3));
        float slo, shi; unpack2(s, slo, shi);
        const float Qn = (slo + shi) * Fr;

        const int nxt = cur ^ 1;
        sP[nxt][j] = mi ? Qn : qown;          // branchless mask
        Esum += mi ? (xb - 127) : 0;          // exact integer magnitude
        cur = nxt;
        __syncthreads();
    }

    // finalize: fwd = Esum*ln2 + log(sum_j S[j]*exp(end[j]))
    const float v = act ? sP[cur][j] * __expf(endT[jj]) : 0.f;
    sRed[j] = v;
    __syncthreads();
    if (j == 0) {
        float tot = 0.f;
        #pragma unroll
        for (int k = 0; k < Tn; ++k) tot += sRed[k];
        g_fwd[b] = (float)((double)Esum * 0.6931471805599453
                           + (double)logf(tot));
    }
}

// ---------------------------------------------------------------------------
// Gold path score: one block per batch, strided gather + block reduce.
// tags may arrive as int32 (JAX silently downgrades int64 without x64 mode)
// or as genuine int64 — sniff the layout (odd 32-bit words all zero => int64).
// ---------------------------------------------------------------------------
__global__ __launch_bounds__(256)
void crf_gold_kernel(const float* __restrict__ emis,
                     const int*   __restrict__ tags32,
                     const int*   __restrict__ mask,
                     const float* __restrict__ trans,
                     const float* __restrict__ startT,
                     const float* __restrict__ endT)
{
    __shared__ double sred[256];
    __shared__ int    scnt[256];
    __shared__ int    s_is64;
    const int b = blockIdx.x, t = threadIdx.x;

    if (t < 32) {
        unsigned hw = (unsigned)tags32[2 * t + 1];
        #pragma unroll
        for (int off = 16; off > 0; off >>= 1)
            hw |= __shfl_down_sync(0xffffffffu, hw, off);
        if (t == 0) s_is64 = (hw == 0u) ? 1 : 0;
    }
    __syncthreads();
    const int is64 = s_is64;
    const size_t base = (size_t)b * Sn;

    const int*   mk = mask + base;
    const float* em = emis + (size_t)b * Sn * Tn;

    double acc = 0.0;
    int cnt = 0;
    for (int i = t; i < Sn; i += 256) {
        const int m = mk[i];
        cnt += m;
        if (i >= 1 && m) {
            const size_t ic = base + (size_t)i;
            const int tp = is64 ? tags32[(ic - 1) << 1] : tags32[ic - 1];
            const int tc = is64 ? tags32[ic << 1]       : tags32[ic];
            acc += (double)trans[tp * Tn + tc] + (double)em[(size_t)i * Tn + tc];
        }
    }
    sred[t] = acc;
    scnt[t] = cnt;
    __syncthreads();
    for (int s2 = 128; s2 > 0; s2 >>= 1) {
        if (t < s2) { sred[t] += sred[t + s2]; scnt[t] += scnt[t + s2]; }
        __syncthreads();
    }
    if (t == 0) {
        const int t0 = is64 ? tags32[base << 1] : tags32[base];
        double g = sred[0] + (double)startT[t0] + (double)em[t0];
        const size_t il = base + (size_t)(scnt[0] - 1);
        const int tl = is64 ? tags32[il << 1] : tags32[il];
        g += (double)endT[tl];
        g_gold[b] = (float)g;
    }
}

// ---------------------------------------------------------------------------
// Final: out = mean(fwd - gold)
// ---------------------------------------------------------------------------
__global__ __launch_bounds__(256)
void crf_final_kernel(float* __restrict__ out)
{
    __shared__ double sred[256];
    const int t = threadIdx.x;
    sred[t] = (double)g_fwd[t] - (double)g_gold[t];
    __syncthreads();
    for (int s2 = 128; s2 > 0; s2 >>= 1) {
        if (t < s2) sred[t] += sred[t + s2];
        __syncthreads();
    }
    if (t == 0) out[0] = (float)(sred[0] / (double)Bn);
}

extern "C" void kernel_launch(void* const* d_in, const int* in_sizes, int n_in,
                              void* d_out, int out_size)
{
    const float* emis   = (const float*)d_in[0];
    const int*   tags32 = (const int*)d_in[1];   // int32 OR int64 viewed as words
    const int*   mask   = (const int*)d_in[2];
    const float* trans  = (const float*)d_in[3];
    const float* startT = (const float*)d_in[4];
    const float* endT   = (const float*)d_in[5];
    float* out = (float*)d_out;

    crf_forward_kernel<<<Bn, 64>>>(emis, mask, trans, startT, endT);
    crf_gold_kernel<<<Bn, 256>>>(emis, tags32, mask, trans, startT, endT);
    crf_final_kernel<<<1, 256>>>(out);
}

// round 9
// speedup vs baseline: 1.8448x; 1.3237x over previous
#include <cuda_runtime.h>

#define Tn 48
#define Sn 2048
#define Bn 256

__device__ float g_delta[Bn];

typedef unsigned long long ull;

__device__ __forceinline__ ull pack2(float lo, float hi) {
    ull r; asm("mov.b64 %0,{%1,%2};" : "=l"(r) : "f"(lo), "f"(hi)); return r;
}
__device__ __forceinline__ void fma2(ull& a, ull b, ull c) {
    asm("fma.rn.f32x2 %0,%1,%2,%0;" : "+l"(a) : "l"(b), "l"(c));
}
__device__ __forceinline__ ull add2(ull a, ull b) {
    ull r; asm("add.rn.f32x2 %0,%1,%2;" : "=l"(r) : "l"(a), "l"(b)); return r;
}
__device__ __forceinline__ void unpack2(ull v, float& lo, float& hi) {
    asm("mov.b64 {%0,%1},%2;" : "=f"(lo), "=f"(hi) : "l"(v));
}

// ---------------------------------------------------------------------------
// Forward + gold fused. 64 threads (2 warps) per batch.
// Forward: linear domain, exponent-only rescaling, 24 FFMA2 inner product,
// alpha double-buffered in shared as plain float[64] read via C++ ulonglong2.
// Chain trims vs R8: own value carried in a register (no qown LDS), the
// normalizer q0 extracted from the first vector load (no scalar LDS), and
// the i+4 prefetch issued between STS and bar.sync so it overlaps the wait.
// Gold: computed post-loop by the same block (32 gather items per thread,
// fp64 block reduce) — rides otherwise-idle time, kills a kernel launch.
// Invariant: alpha_i[k] = Esum*ln2 + log(S_i[k]) (exact integer exponent).
// ---------------------------------------------------------------------------
__global__ __launch_bounds__(64)
void crf_fused_kernel(const float* __restrict__ emis,
                      const int*   __restrict__ tags32,
                      const int*   __restrict__ mask,
                      const float* __restrict__ trans,
                      const float* __restrict__ startT,
                      const float* __restrict__ endT)
{
    __shared__ __align__(16) float sP[2][64];
    __shared__ float  sRed[64];
    __shared__ double sG[64];
    __shared__ int    sC[64];
    __shared__ int    s_is64;

    const int b = blockIdx.x;
    const int j = threadIdx.x;
    const bool act = (j < Tn);
    const int jj = act ? j : 0;

    // int64-vs-int32 sniff for tags (odd 32-bit words all zero => int64)
    if (j < 32) {
        unsigned hw = (unsigned)tags32[2 * j + 1];
        #pragma unroll
        for (int off = 16; off > 0; off >>= 1)
            hw |= __shfl_down_sync(0xffffffffu, hw, off);
        if (j == 0) s_is64 = (hw == 0u) ? 1 : 0;
    }

    // E column packed over k-pairs
    ull Epk[Tn / 2];
    #pragma unroll
    for (int p = 0; p < Tn / 2; ++p)
        Epk[p] = pack2(__expf(trans[(2 * p)     * Tn + jj]),
                       __expf(trans[(2 * p + 1) * Tn + jj]));

    const float* em_b = emis + (size_t)b * Sn * Tn;
    const int*   mk_b = mask + (size_t)b * Sn;

    // init
    float own = __expf(startT[jj] + em_b[jj]);   // alpha_0[j], register-carried
    sP[0][j] = own;
    int Esum = 0;

    // prefetch pipeline (distance 4)
    float f0 = __expf(em_b[1 * Tn + jj]);
    float f1 = __expf(em_b[2 * Tn + jj]);
    float f2 = __expf(em_b[3 * Tn + jj]);
    float f3 = __expf(em_b[4 * Tn + jj]);
    int   m0 = mk_b[1], m1 = mk_b[2], m2 = mk_b[3], m3 = mk_b[4];

    __syncthreads();

    int cur = 0;
    #pragma unroll 2
    for (int i = 1; i < Sn; ++i) {
        const float F  = f0;
        const int   mi = m0;

        const ulonglong2* __restrict__ p2 = (const ulonglong2*)sP[cur];

        ull a0 = 0ull, a1 = 0ull, a2 = 0ull, a3 = 0ull;
        ull q00 = 0ull;
        #pragma unroll
        for (int m = 0; m < 12; m += 2) {
            const ulonglong2 qa = p2[m + 0];
            const ulonglong2 qb = p2[m + 1];
            if (m == 0) q00 = qa.x;            // (alpha0, alpha1)
            fma2(a0, qa.x, Epk[2 * m + 0]);
            fma2(a1, qa.y, Epk[2 * m + 1]);
            fma2(a2, qb.x, Epk[2 * m + 2]);
            fma2(a3, qb.y, Epk[2 * m + 3]);
        }

        // normalizer from exponent of alpha[0] (lo half of q00): exact
        float q0f, q1f; unpack2(q00, q0f, q1f);
        const int  xb = __float_as_int(q0f) >> 23;
        const float r = __int_as_float((254 - xb) << 23);
        const float Fr = F * r;

        const ull s = add2(add2(a0, a1), add2(a2, a3));
        float slo, shi; unpack2(s, slo, shi);
        const float Qn = (slo + shi) * Fr;

        const float out = mi ? Qn : own;       // register select, no LDS
        own = out;
        const int nxt = cur ^ 1;
        sP[nxt][j] = out;
        Esum += mi ? (xb - 127) : 0;

        // prefetch for i+4 (issues before the barrier -> overlaps the wait)
        f0 = f1; f1 = f2; f2 = f3;
        m0 = m1; m1 = m2; m2 = m3;
        const int ip = (i + 4 < Sn) ? (i + 4) : (Sn - 1);
        f3 = __expf(em_b[(size_t)ip * Tn + jj]);
        m3 = mk_b[ip];

        cur = nxt;
        __syncthreads();
    }

    // ---- forward finalize ----
    sRed[j] = act ? sP[cur][j] * __expf(endT[jj]) : 0.f;

    // ---- gold (post-loop, latency-tolerant gathers) ----
    const int is64 = s_is64;
    const size_t base = (size_t)b * Sn;
    double gacc = 0.0;
    int cnt = 0;
    for (int i = j; i < Sn; i += 64) {
        const int m = mk_b[i];
        cnt += m;
        if (i >= 1 && m) {
            const size_t ic = base + (size_t)i;
            const int tp = is64 ? tags32[(ic - 1) << 1] : tags32[ic - 1];
            const int tc = is64 ? tags32[ic << 1]       : tags32[ic];
            gacc += (double)trans[tp * Tn + tc]
                  + (double)em_b[(size_t)i * Tn + tc];
        }
    }
    sG[j] = gacc;
    sC[j] = cnt;
    __syncthreads();
    for (int s2 = 32; s2 > 0; s2 >>= 1) {
        if (j < s2) { sG[j] += sG[j + s2]; sC[j] += sC[j + s2]; }
        __syncthreads();
    }

    if (j == 0) {
        float tot = 0.f;
        #pragma unroll
        for (int k = 0; k < Tn; ++k) tot += sRed[k];
        const double fwd = (double)Esum * 0.6931471805599453
                         + (double)logf(tot);

        const int t0 = is64 ? tags32[base << 1] : tags32[base];
        double gold = sG[0] + (double)startT[t0] + (double)em_b[t0];
        const size_t il = base + (size_t)(sC[0] - 1);
        const int tl = is64 ? tags32[il << 1] : tags32[il];
        gold += (double)endT[tl];

        g_delta[b] = (float)(fwd - gold);
    }
}

// ---------------------------------------------------------------------------
// Final: out = mean(g_delta)
// ---------------------------------------------------------------------------
__global__ __launch_bounds__(256)
void crf_final_kernel(float* __restrict__ out)
{
    __shared__ double sred[256];
    const int t = threadIdx.x;
    sred[t] = (double)g_delta[t];
    __syncthreads();
    for (int s2 = 128; s2 > 0; s2 >>= 1) {
        if (t < s2) sred[t] += sred[t + s2];
        __syncthreads();
    }
    if (t == 0) out[0] = (float)(sred[0] / (double)Bn);
}

extern "C" void kernel_launch(void* const* d_in, const int* in_sizes, int n_in,
                              void* d_out, int out_size)
{
    const float* emis   = (const float*)d_in[0];
    const int*   tags32 = (const int*)d_in[1];   // int32 OR int64 viewed as words
    const int*   mask   = (const int*)d_in[2];
    const float* trans  = (const float*)d_in[3];
    const float* startT = (const float*)d_in[4];
    const float* endT   = (const float*)d_in[5];
    float* out = (float*)d_out;

    crf_fused_kernel<<<Bn, 64>>>(emis, tags32, mask, trans, startT, endT);
    crf_final_kernel<<<1, 256>>>(out);
}